// round 14
// baseline (speedup 1.0000x reference)
#include <cuda_runtime.h>
#include <cuda_fp16.h>

#define GN     128
#define GMASK  127
#define NCELLS (GN * GN * GN)

// grid scratch: one 16B record per cell = 8 fp16 features. 32 MB.
__device__ uint4 g_gridh[NCELLS];

__device__ __forceinline__ unsigned h2_to_u(__half2 h) {
    return *reinterpret_cast<unsigned*>(&h);
}
__device__ __forceinline__ __half2 u_to_h2(unsigned u) {
    return *reinterpret_cast<__half2*>(&u);
}

// ---------------- P2G: 4 lanes/point, 8 points/warp, z-pair REDs from one lane ------------
// lane = p*4 + s;  s: ox=bit1, oy=bit0.  Each lane handles nodes (ox,oy,0) and (ox,oy,1):
// two red.v4.f16x2 to ADJACENT records nid,nid+1 (same LTS sector 50% of the time),
// moving the REDG rate toward the single-addr constant.
__global__ __launch_bounds__(256)
void p2g_pair(const float* __restrict__ pos,
              const float4* __restrict__ feat4, int n) {
    int lane = threadIdx.x & 31;
    int warp = (blockIdx.x * blockDim.x + threadIdx.x) >> 5;
    int i = warp * 8 + (lane >> 2);
    if (i >= n) return;

    int s = lane & 3;
    int ox = (s >> 1) & 1, oy = s & 1;

    float rx = __ldg(&pos[3 * i + 0]) * (float)GN;
    float ry = __ldg(&pos[3 * i + 1]) * (float)GN;
    float rz = __ldg(&pos[3 * i + 2]) * (float)GN;
    int bx = (int)rx, by = (int)ry, bz = (int)rz;
    float fx = rx - (float)bx, fy = ry - (float)by, fz = rz - (float)bz;

    float wxy = (ox ? fx : 1.0f - fx) * (oy ? fy : 1.0f - fy);
    float w0 = wxy * (1.0f - fz);   // oz = 0
    float w1 = wxy * fz;            // oz = 1

    float4 f0 = __ldg(&feat4[2 * i + 0]);
    float4 f1 = __ldg(&feat4[2 * i + 1]);

    int nx = (bx + ox) & GMASK;
    int ny = (by + oy) & GMASK;
    int nid0 = ((nx << 7 | ny) << 7) | bz;
    int nid1 = ((nx << 7 | ny) << 7) | ((bz + 1) & GMASK);

    __half2 a01 = __floats2half2_rn(w0 * f0.x, w0 * f0.y);
    __half2 a23 = __floats2half2_rn(w0 * f0.z, w0 * f0.w);
    __half2 a45 = __floats2half2_rn(w0 * f1.x, w0 * f1.y);
    __half2 a67 = __floats2half2_rn(w0 * f1.z, w0 * f1.w);
    asm volatile(
        "red.global.add.noftz.v4.f16x2 [%0], {%1, %2, %3, %4};"
        :: "l"(&g_gridh[nid0]),
           "r"(h2_to_u(a01)), "r"(h2_to_u(a23)),
           "r"(h2_to_u(a45)), "r"(h2_to_u(a67))
        : "memory");

    __half2 b01 = __floats2half2_rn(w1 * f0.x, w1 * f0.y);
    __half2 b23 = __floats2half2_rn(w1 * f0.z, w1 * f0.w);
    __half2 b45 = __floats2half2_rn(w1 * f1.x, w1 * f1.y);
    __half2 b67 = __floats2half2_rn(w1 * f1.z, w1 * f1.w);
    asm volatile(
        "red.global.add.noftz.v4.f16x2 [%0], {%1, %2, %3, %4};"
        :: "l"(&g_gridh[nid1]),
           "r"(h2_to_u(b01)), "r"(h2_to_u(b23)),
           "r"(h2_to_u(b45)), "r"(h2_to_u(b67))
        : "memory");
}

// ---------------- G2P: 4 lanes/point, 4 points/thread, half2 math, deep LTS queue ---------
// lane = pp*4 + s;  s: oy=bit1, oz=bit0.  Thread handles i_m = warp*32 + pp + 8m.
// 8 independent 16B grid loads in flight per thread.
struct PtCtxH { __half2 wA2, wB2; int nidA, nidB; };

__device__ __forceinline__ PtCtxH g2p_setup_h(const float* __restrict__ pos, int i,
                                              int oy, int oz) {
    float rx = __ldg(&pos[3 * i + 0]) * (float)GN;
    float ry = __ldg(&pos[3 * i + 1]) * (float)GN;
    float rz = __ldg(&pos[3 * i + 2]) * (float)GN;
    int bx = (int)rx, by = (int)ry, bz = (int)rz;
    float fx = rx - (float)bx, fy = ry - (float)by, fz = rz - (float)bz;

    float wyz = (oy ? fy : 1.0f - fy) * (oz ? fz : 1.0f - fz);
    PtCtxH c;
    c.wA2 = __half2half2(__float2half_rn((1.0f - fx) * wyz));
    c.wB2 = __half2half2(__float2half_rn(fx * wyz));
    int ny = (by + oy) & GMASK;
    int nz = (bz + oz) & GMASK;
    c.nidA = ((bx << 7 | ny) << 7) | nz;
    c.nidB = ((((bx + 1) & GMASK) << 7 | ny) << 7) | nz;
    return c;
}

__device__ __forceinline__ float2 g2p_combine_h(const uint4& ra, const uint4& rb,
                                                const PtCtxH& c, bool soz, bool soy) {
    const __half2* ha = reinterpret_cast<const __half2*>(&ra);
    const __half2* hb = reinterpret_cast<const __half2*>(&rb);
    __half2 v0 = __hfma2(hb[0], c.wB2, __hmul2(ha[0], c.wA2));
    __half2 v1 = __hfma2(hb[1], c.wB2, __hmul2(ha[1], c.wA2));
    __half2 v2 = __hfma2(hb[2], c.wB2, __hmul2(ha[2], c.wA2));
    __half2 v3 = __hfma2(hb[3], c.wB2, __hmul2(ha[3], c.wA2));

    unsigned t, r;
    __half2 a0, a1;
    t = h2_to_u(soz ? v0 : v2);
    r = __shfl_xor_sync(0xffffffffu, t, 1);
    a0 = __hadd2(soz ? v2 : v0, u_to_h2(r));
    t = h2_to_u(soz ? v1 : v3);
    r = __shfl_xor_sync(0xffffffffu, t, 1);
    a1 = __hadd2(soz ? v3 : v1, u_to_h2(r));

    t = h2_to_u(soy ? a0 : a1);
    r = __shfl_xor_sync(0xffffffffu, t, 2);
    __half2 b = __hadd2(soy ? a1 : a0, u_to_h2(r));

    return __half22float2(b);
}

__global__ __launch_bounds__(256, 4)
void g2p_h4(const float* __restrict__ pos,
            float2* __restrict__ out2, int n) {
    int lane = threadIdx.x & 31;
    int warp = (blockIdx.x * blockDim.x + threadIdx.x) >> 5;
    int pp = lane >> 2;
    int s = lane & 3;
    int oy = (s >> 1) & 1;
    int oz = s & 1;
    bool soz = oz != 0, soy = oy != 0;

    int base = warp * 32 + pp;
    int i0 = base, i1 = base + 8, i2 = base + 16, i3 = base + 24;
    bool a0 = i0 < n, a1 = i1 < n, a2 = i2 < n, a3 = i3 < n;
    int ic0 = a0 ? i0 : (n - 1), ic1 = a1 ? i1 : (n - 1);
    int ic2 = a2 ? i2 : (n - 1), ic3 = a3 ? i3 : (n - 1);

    PtCtxH c0 = g2p_setup_h(pos, ic0, oy, oz);
    PtCtxH c1 = g2p_setup_h(pos, ic1, oy, oz);
    PtCtxH c2 = g2p_setup_h(pos, ic2, oy, oz);
    PtCtxH c3 = g2p_setup_h(pos, ic3, oy, oz);

    // 8 independent 16B loads
    uint4 rA0 = __ldg(&g_gridh[c0.nidA]);
    uint4 rB0 = __ldg(&g_gridh[c0.nidB]);
    uint4 rA1 = __ldg(&g_gridh[c1.nidA]);
    uint4 rB1 = __ldg(&g_gridh[c1.nidB]);
    uint4 rA2 = __ldg(&g_gridh[c2.nidA]);
    uint4 rB2 = __ldg(&g_gridh[c2.nidB]);
    uint4 rA3 = __ldg(&g_gridh[c3.nidA]);
    uint4 rB3 = __ldg(&g_gridh[c3.nidB]);

    float2 r0 = g2p_combine_h(rA0, rB0, c0, soz, soy);
    float2 r1 = g2p_combine_h(rA1, rB1, c1, soz, soy);
    float2 r2 = g2p_combine_h(rA2, rB2, c2, soz, soy);
    float2 r3 = g2p_combine_h(rA3, rB3, c3, soz, soy);

    int cpair = oz * 2 + oy;
    if (a0) out2[4 * (size_t)i0 + cpair] = r0;
    if (a1) out2[4 * (size_t)i1 + cpair] = r1;
    if (a2) out2[4 * (size_t)i2 + cpair] = r2;
    if (a3) out2[4 * (size_t)i3 + cpair] = r3;
}

extern "C" void kernel_launch(void* const* d_in, const int* in_sizes, int n_in,
                              void* d_out, int out_size) {
    const float* pos  = (const float*)d_in[0];   // [N,3] f32
    const float* feat = (const float*)d_in[1];   // [N,8] f32
    float* out        = (float*)d_out;           // [N,8] f32
    int n = in_sizes[0] / 3;

    void* gptr = nullptr;
    cudaGetSymbolAddress(&gptr, g_gridh);
    cudaMemsetAsync(gptr, 0, (size_t)NCELLS * sizeof(uint4), 0);

    // p2g: 4 lanes/point -> 64 points per 256-thread block
    int pb = (n + 63) / 64;
    p2g_pair<<<pb, 256>>>(pos, (const float4*)feat, n);

    // g2p: 4 lanes/point, 4 pts/thread -> 256 points per 256-thread block
    int gb = (n + 255) / 256;
    g2p_h4<<<gb, 256>>>(pos, (float2*)out, n);
}

// round 15
// speedup vs baseline: 1.0301x; 1.0301x over previous
#include <cuda_runtime.h>
#include <cuda_fp16.h>

#define GN     128
#define GMASK  127
#define NCELLS (GN * GN * GN)

// grid scratch: one 16B record per cell = 8 fp16 features. 32 MB.
__device__ uint4 g_gridh[NCELLS];

__device__ __forceinline__ unsigned h2_to_u(__half2 h) {
    return *reinterpret_cast<unsigned*>(&h);
}
__device__ __forceinline__ __half2 u_to_h2(unsigned u) {
    return *reinterpret_cast<__half2*>(&u);
}

// ---------------- P2G: 8 lanes/point, 4 points/warp, one 16B fp16 red per node ------------
// lane = p*8 + s;  s = node id: ox=bit2, oy=bit1, oz=bit0.
// One RED per lane = measured REDG spread-rate floor (~36us). r14 proved pairing regresses.
__global__ __launch_bounds__(256)
void p2g_h(const float* __restrict__ pos,
           const float4* __restrict__ feat4, int n) {
    int lane = threadIdx.x & 31;
    int warp = (blockIdx.x * blockDim.x + threadIdx.x) >> 5;
    int i = warp * 4 + (lane >> 3);
    if (i >= n) return;

    int s = lane & 7;
    int ox = (s >> 2) & 1, oy = (s >> 1) & 1, oz = s & 1;

    float rx = __ldg(&pos[3 * i + 0]) * (float)GN;
    float ry = __ldg(&pos[3 * i + 1]) * (float)GN;
    float rz = __ldg(&pos[3 * i + 2]) * (float)GN;
    int bx = (int)rx, by = (int)ry, bz = (int)rz;
    float fx = rx - (float)bx, fy = ry - (float)by, fz = rz - (float)bz;

    float w = (ox ? fx : 1.0f - fx) * (oy ? fy : 1.0f - fy) * (oz ? fz : 1.0f - fz);

    float4 f0 = __ldg(&feat4[2 * i + 0]);
    float4 f1 = __ldg(&feat4[2 * i + 1]);

    int nx = (bx + ox) & GMASK;
    int ny = (by + oy) & GMASK;
    int nz = (bz + oz) & GMASK;
    int nid = ((nx << 7 | ny) << 7) | nz;

    __half2 h01 = __floats2half2_rn(w * f0.x, w * f0.y);
    __half2 h23 = __floats2half2_rn(w * f0.z, w * f0.w);
    __half2 h45 = __floats2half2_rn(w * f1.x, w * f1.y);
    __half2 h67 = __floats2half2_rn(w * f1.z, w * f1.w);

    asm volatile(
        "red.global.add.noftz.v4.f16x2 [%0], {%1, %2, %3, %4};"
        :: "l"(&g_gridh[nid]),
           "r"(h2_to_u(h01)), "r"(h2_to_u(h23)),
           "r"(h2_to_u(h45)), "r"(h2_to_u(h67))
        : "memory");
}

// ---------------- G2P: 4 lanes/point, 4 points/thread, half2 math (best measured: 28.0us) --
// lane = pp*4 + s;  s: oy=bit1, oz=bit0.  Thread handles i_m = warp*32 + pp + 8m.
struct PtCtxH { __half2 wA2, wB2; int nidA, nidB; };

__device__ __forceinline__ PtCtxH g2p_setup_h(const float* __restrict__ pos, int i,
                                              int oy, int oz) {
    float rx = __ldg(&pos[3 * i + 0]) * (float)GN;
    float ry = __ldg(&pos[3 * i + 1]) * (float)GN;
    float rz = __ldg(&pos[3 * i + 2]) * (float)GN;
    int bx = (int)rx, by = (int)ry, bz = (int)rz;
    float fx = rx - (float)bx, fy = ry - (float)by, fz = rz - (float)bz;

    float wyz = (oy ? fy : 1.0f - fy) * (oz ? fz : 1.0f - fz);
    PtCtxH c;
    c.wA2 = __half2half2(__float2half_rn((1.0f - fx) * wyz));
    c.wB2 = __half2half2(__float2half_rn(fx * wyz));
    int ny = (by + oy) & GMASK;
    int nz = (bz + oz) & GMASK;
    c.nidA = ((bx << 7 | ny) << 7) | nz;
    c.nidB = ((((bx + 1) & GMASK) << 7 | ny) << 7) | nz;
    return c;
}

__device__ __forceinline__ float2 g2p_combine_h(const uint4& ra, const uint4& rb,
                                                const PtCtxH& c, bool soz, bool soy) {
    const __half2* ha = reinterpret_cast<const __half2*>(&ra);
    const __half2* hb = reinterpret_cast<const __half2*>(&rb);
    __half2 v0 = __hfma2(hb[0], c.wB2, __hmul2(ha[0], c.wA2));
    __half2 v1 = __hfma2(hb[1], c.wB2, __hmul2(ha[1], c.wA2));
    __half2 v2 = __hfma2(hb[2], c.wB2, __hmul2(ha[2], c.wA2));
    __half2 v3 = __hfma2(hb[3], c.wB2, __hmul2(ha[3], c.wA2));

    unsigned t, r;
    __half2 a0, a1;
    t = h2_to_u(soz ? v0 : v2);
    r = __shfl_xor_sync(0xffffffffu, t, 1);
    a0 = __hadd2(soz ? v2 : v0, u_to_h2(r));
    t = h2_to_u(soz ? v1 : v3);
    r = __shfl_xor_sync(0xffffffffu, t, 1);
    a1 = __hadd2(soz ? v3 : v1, u_to_h2(r));

    t = h2_to_u(soy ? a0 : a1);
    r = __shfl_xor_sync(0xffffffffu, t, 2);
    __half2 b = __hadd2(soy ? a1 : a0, u_to_h2(r));

    return __half22float2(b);
}

__global__ __launch_bounds__(256, 4)
void g2p_h4(const float* __restrict__ pos,
            float2* __restrict__ out2, int n) {
    int lane = threadIdx.x & 31;
    int warp = (blockIdx.x * blockDim.x + threadIdx.x) >> 5;
    int pp = lane >> 2;
    int s = lane & 3;
    int oy = (s >> 1) & 1;
    int oz = s & 1;
    bool soz = oz != 0, soy = oy != 0;

    int base = warp * 32 + pp;
    int i0 = base, i1 = base + 8, i2 = base + 16, i3 = base + 24;
    bool a0 = i0 < n, a1 = i1 < n, a2 = i2 < n, a3 = i3 < n;
    int ic0 = a0 ? i0 : (n - 1), ic1 = a1 ? i1 : (n - 1);
    int ic2 = a2 ? i2 : (n - 1), ic3 = a3 ? i3 : (n - 1);

    PtCtxH c0 = g2p_setup_h(pos, ic0, oy, oz);
    PtCtxH c1 = g2p_setup_h(pos, ic1, oy, oz);
    PtCtxH c2 = g2p_setup_h(pos, ic2, oy, oz);
    PtCtxH c3 = g2p_setup_h(pos, ic3, oy, oz);

    // 8 independent 16B loads
    uint4 rA0 = __ldg(&g_gridh[c0.nidA]);
    uint4 rB0 = __ldg(&g_gridh[c0.nidB]);
    uint4 rA1 = __ldg(&g_gridh[c1.nidA]);
    uint4 rB1 = __ldg(&g_gridh[c1.nidB]);
    uint4 rA2 = __ldg(&g_gridh[c2.nidA]);
    uint4 rB2 = __ldg(&g_gridh[c2.nidB]);
    uint4 rA3 = __ldg(&g_gridh[c3.nidA]);
    uint4 rB3 = __ldg(&g_gridh[c3.nidB]);

    float2 r0 = g2p_combine_h(rA0, rB0, c0, soz, soy);
    float2 r1 = g2p_combine_h(rA1, rB1, c1, soz, soy);
    float2 r2 = g2p_combine_h(rA2, rB2, c2, soz, soy);
    float2 r3 = g2p_combine_h(rA3, rB3, c3, soz, soy);

    int cpair = oz * 2 + oy;
    if (a0) out2[4 * (size_t)i0 + cpair] = r0;
    if (a1) out2[4 * (size_t)i1 + cpair] = r1;
    if (a2) out2[4 * (size_t)i2 + cpair] = r2;
    if (a3) out2[4 * (size_t)i3 + cpair] = r3;
}

extern "C" void kernel_launch(void* const* d_in, const int* in_sizes, int n_in,
                              void* d_out, int out_size) {
    const float* pos  = (const float*)d_in[0];   // [N,3] f32
    const float* feat = (const float*)d_in[1];   // [N,8] f32
    float* out        = (float*)d_out;           // [N,8] f32
    int n = in_sizes[0] / 3;

    void* gptr = nullptr;
    cudaGetSymbolAddress(&gptr, g_gridh);
    cudaMemsetAsync(gptr, 0, (size_t)NCELLS * sizeof(uint4), 0);

    // p2g: 8 lanes/point -> 32 points per 256-thread block
    int pb = (n + 31) / 32;
    p2g_h<<<pb, 256>>>(pos, (const float4*)feat, n);

    // g2p: 4 lanes/point, 4 pts/thread -> 256 points per 256-thread block
    int gb = (n + 255) / 256;
    g2p_h4<<<gb, 256>>>(pos, (float2*)out, n);
}

// round 16
// speedup vs baseline: 1.0846x; 1.0529x over previous
#include <cuda_runtime.h>
#include <cuda_fp16.h>

#define GN     128
#define GMASK  127
#define NCELLS (GN * GN * GN)

// grid scratch: 8 fp16 feats per cell, 2x2x2-blocked layout:
// one 128B line holds the 8 records of a 2x2x2 cell block. 32 MB.
__device__ uint4 g_gridh[NCELLS];

__device__ __forceinline__ int blocked_nid(int x, int y, int z) {
    return (((x >> 1) << 15) | ((y >> 1) << 9) | ((z >> 1) << 3))
         | ((x & 1) << 2) | ((y & 1) << 1) | (z & 1);
}

__device__ __forceinline__ unsigned h2_to_u(__half2 h) {
    return *reinterpret_cast<unsigned*>(&h);
}
__device__ __forceinline__ __half2 u_to_h2(unsigned u) {
    return *reinterpret_cast<__half2*>(&u);
}

// ---------------- P2G: 8 lanes/point, 4 points/warp, blocked grid ------------
// lane = p*8 + s;  s = node id: ox=bit2, oy=bit1, oz=bit0.
// With the 2x2x2 layout a point's 8 REDs span E[3.375] lines (1 line for 12.5%).
__global__ __launch_bounds__(256)
void p2g_h(const float* __restrict__ pos,
           const float4* __restrict__ feat4, int n) {
    int lane = threadIdx.x & 31;
    int warp = (blockIdx.x * blockDim.x + threadIdx.x) >> 5;
    int i = warp * 4 + (lane >> 3);
    if (i >= n) return;

    int s = lane & 7;
    int ox = (s >> 2) & 1, oy = (s >> 1) & 1, oz = s & 1;

    float rx = __ldg(&pos[3 * i + 0]) * (float)GN;
    float ry = __ldg(&pos[3 * i + 1]) * (float)GN;
    float rz = __ldg(&pos[3 * i + 2]) * (float)GN;
    int bx = (int)rx, by = (int)ry, bz = (int)rz;
    float fx = rx - (float)bx, fy = ry - (float)by, fz = rz - (float)bz;

    float w = (ox ? fx : 1.0f - fx) * (oy ? fy : 1.0f - fy) * (oz ? fz : 1.0f - fz);

    float4 f0 = __ldg(&feat4[2 * i + 0]);
    float4 f1 = __ldg(&feat4[2 * i + 1]);

    int nx = (bx + ox) & GMASK;
    int ny = (by + oy) & GMASK;
    int nz = (bz + oz) & GMASK;
    int nid = blocked_nid(nx, ny, nz);

    __half2 h01 = __floats2half2_rn(w * f0.x, w * f0.y);
    __half2 h23 = __floats2half2_rn(w * f0.z, w * f0.w);
    __half2 h45 = __floats2half2_rn(w * f1.x, w * f1.y);
    __half2 h67 = __floats2half2_rn(w * f1.z, w * f1.w);

    asm volatile(
        "red.global.add.noftz.v4.f16x2 [%0], {%1, %2, %3, %4};"
        :: "l"(&g_gridh[nid]),
           "r"(h2_to_u(h01)), "r"(h2_to_u(h23)),
           "r"(h2_to_u(h45)), "r"(h2_to_u(h67))
        : "memory");
}

// ---------------- G2P: 4 lanes/point, 4 points/thread, blocked grid ----------
// lane = pp*4 + s;  s: oy=bit1, oz=bit0.  Thread handles i_m = warp*32 + pp + 8m.
struct PtCtxH { __half2 wA2, wB2; int nidA, nidB; };

__device__ __forceinline__ PtCtxH g2p_setup_h(const float* __restrict__ pos, int i,
                                              int oy, int oz) {
    float rx = __ldg(&pos[3 * i + 0]) * (float)GN;
    float ry = __ldg(&pos[3 * i + 1]) * (float)GN;
    float rz = __ldg(&pos[3 * i + 2]) * (float)GN;
    int bx = (int)rx, by = (int)ry, bz = (int)rz;
    float fx = rx - (float)bx, fy = ry - (float)by, fz = rz - (float)bz;

    float wyz = (oy ? fy : 1.0f - fy) * (oz ? fz : 1.0f - fz);
    PtCtxH c;
    c.wA2 = __half2half2(__float2half_rn((1.0f - fx) * wyz));
    c.wB2 = __half2half2(__float2half_rn(fx * wyz));
    int ny = (by + oy) & GMASK;
    int nz = (bz + oz) & GMASK;
    c.nidA = blocked_nid(bx, ny, nz);
    c.nidB = blocked_nid((bx + 1) & GMASK, ny, nz);
    return c;
}

__device__ __forceinline__ float2 g2p_combine_h(const uint4& ra, const uint4& rb,
                                                const PtCtxH& c, bool soz, bool soy) {
    const __half2* ha = reinterpret_cast<const __half2*>(&ra);
    const __half2* hb = reinterpret_cast<const __half2*>(&rb);
    __half2 v0 = __hfma2(hb[0], c.wB2, __hmul2(ha[0], c.wA2));
    __half2 v1 = __hfma2(hb[1], c.wB2, __hmul2(ha[1], c.wA2));
    __half2 v2 = __hfma2(hb[2], c.wB2, __hmul2(ha[2], c.wA2));
    __half2 v3 = __hfma2(hb[3], c.wB2, __hmul2(ha[3], c.wA2));

    unsigned t, r;
    __half2 a0, a1;
    t = h2_to_u(soz ? v0 : v2);
    r = __shfl_xor_sync(0xffffffffu, t, 1);
    a0 = __hadd2(soz ? v2 : v0, u_to_h2(r));
    t = h2_to_u(soz ? v1 : v3);
    r = __shfl_xor_sync(0xffffffffu, t, 1);
    a1 = __hadd2(soz ? v3 : v1, u_to_h2(r));

    t = h2_to_u(soy ? a0 : a1);
    r = __shfl_xor_sync(0xffffffffu, t, 2);
    __half2 b = __hadd2(soy ? a1 : a0, u_to_h2(r));

    return __half22float2(b);
}

__global__ __launch_bounds__(256, 4)
void g2p_h4(const float* __restrict__ pos,
            float2* __restrict__ out2, int n) {
    int lane = threadIdx.x & 31;
    int warp = (blockIdx.x * blockDim.x + threadIdx.x) >> 5;
    int pp = lane >> 2;
    int s = lane & 3;
    int oy = (s >> 1) & 1;
    int oz = s & 1;
    bool soz = oz != 0, soy = oy != 0;

    int base = warp * 32 + pp;
    int i0 = base, i1 = base + 8, i2 = base + 16, i3 = base + 24;
    bool a0 = i0 < n, a1 = i1 < n, a2 = i2 < n, a3 = i3 < n;
    int ic0 = a0 ? i0 : (n - 1), ic1 = a1 ? i1 : (n - 1);
    int ic2 = a2 ? i2 : (n - 1), ic3 = a3 ? i3 : (n - 1);

    PtCtxH c0 = g2p_setup_h(pos, ic0, oy, oz);
    PtCtxH c1 = g2p_setup_h(pos, ic1, oy, oz);
    PtCtxH c2 = g2p_setup_h(pos, ic2, oy, oz);
    PtCtxH c3 = g2p_setup_h(pos, ic3, oy, oz);

    // 8 independent 16B loads; with blocked layout the A/B pair often shares a line
    uint4 rA0 = __ldg(&g_gridh[c0.nidA]);
    uint4 rB0 = __ldg(&g_gridh[c0.nidB]);
    uint4 rA1 = __ldg(&g_gridh[c1.nidA]);
    uint4 rB1 = __ldg(&g_gridh[c1.nidB]);
    uint4 rA2 = __ldg(&g_gridh[c2.nidA]);
    uint4 rB2 = __ldg(&g_gridh[c2.nidB]);
    uint4 rA3 = __ldg(&g_gridh[c3.nidA]);
    uint4 rB3 = __ldg(&g_gridh[c3.nidB]);

    float2 r0 = g2p_combine_h(rA0, rB0, c0, soz, soy);
    float2 r1 = g2p_combine_h(rA1, rB1, c1, soz, soy);
    float2 r2 = g2p_combine_h(rA2, rB2, c2, soz, soy);
    float2 r3 = g2p_combine_h(rA3, rB3, c3, soz, soy);

    int cpair = oz * 2 + oy;
    if (a0) out2[4 * (size_t)i0 + cpair] = r0;
    if (a1) out2[4 * (size_t)i1 + cpair] = r1;
    if (a2) out2[4 * (size_t)i2 + cpair] = r2;
    if (a3) out2[4 * (size_t)i3 + cpair] = r3;
}

extern "C" void kernel_launch(void* const* d_in, const int* in_sizes, int n_in,
                              void* d_out, int out_size) {
    const float* pos  = (const float*)d_in[0];   // [N,3] f32
    const float* feat = (const float*)d_in[1];   // [N,8] f32
    float* out        = (float*)d_out;           // [N,8] f32
    int n = in_sizes[0] / 3;

    void* gptr = nullptr;
    cudaGetSymbolAddress(&gptr, g_gridh);
    cudaMemsetAsync(gptr, 0, (size_t)NCELLS * sizeof(uint4), 0);

    // p2g: 8 lanes/point -> 32 points per 256-thread block
    int pb = (n + 31) / 32;
    p2g_h<<<pb, 256>>>(pos, (const float4*)feat, n);

    // g2p: 4 lanes/point, 4 pts/thread -> 256 points per 256-thread block
    int gb = (n + 255) / 256;
    g2p_h4<<<gb, 256>>>(pos, (float2*)out, n);
}